// round 15
// baseline (speedup 1.0000x reference)
#include <cuda_runtime.h>
#include <cstdint>

#define NSP     2048
#define BATCH   64
#define NSTEP   1000
#define KEX     32            // steps between ghost exchanges
#define GW      64            // ghost width per side (= 2 * KEX)
#define OWNW    128           // owned elems per compute warp
#define EPT     8             // elems per thread
#define CWARPS  8             // compute warps
#define THREADS 288           // 8 compute + 1 writer warp
#define OWN_CTA 1024          // owned per CTA (half row)
#define NBUF    16            // staging ring depth (frames)
#define FB      4             // frames per writer batch
#define NBATCH  (NSTEP / FB)  // 250

typedef unsigned long long u64;

struct Smem {
    float ring[NBUF][OWN_CTA];   // 64 KB staging ring
    float sh_ex[2][OWN_CTA];     // 8 KB exchange staging
    u64   mbar[2];               // cluster exchange handshake
    u64   mb_st;                 // staging-batch barrier (count = CWARPS)
    int   k_done;                // last batch whose TMA reads completed
};

__device__ __forceinline__ u64 pk(float lo, float hi) {
    u64 r; asm("mov.b64 %0,{%1,%2};" : "=l"(r) : "f"(lo), "f"(hi)); return r;
}
__device__ __forceinline__ void upk(u64 v, float& lo, float& hi) {
    asm("mov.b64 {%0,%1},%2;" : "=f"(lo), "=f"(hi) : "l"(v));
}
__device__ __forceinline__ u64 fma2(u64 a, u64 b, u64 c) {
    u64 d; asm("fma.rn.f32x2 %0,%1,%2,%3;" : "=l"(d) : "l"(a), "l"(b), "l"(c)); return d;
}
__device__ __forceinline__ u64 add2(u64 a, u64 b) {
    u64 d; asm("add.rn.f32x2 %0,%1,%2;" : "=l"(d) : "l"(a), "l"(b)); return d;
}
__device__ __forceinline__ u64 mul2(u64 a, u64 b) {
    u64 d; asm("mul.rn.f32x2 %0,%1,%2;" : "=l"(d) : "l"(a), "l"(b)); return d;
}

// branch-free predicated pair of 16B global streaming stores
__device__ __forceinline__ void st2_pred(int pred, float* p,
                                         u64 a, u64 b, u64 c, u64 d) {
    asm volatile(
        "{\n\t.reg .pred q;\n\t"
        "setp.ne.s32 q, %0, 0;\n\t"
        "@q st.global.cs.v2.u64 [%1], {%2,%3};\n\t"
        "@q st.global.cs.v2.u64 [%4], {%5,%6};\n\t}"
        :: "r"(pred), "l"(p), "l"(a), "l"(b), "l"(p + 4), "l"(c), "l"(d)
        : "memory");
}

// branch-free predicated pair of 16B shared stores (ring staging)
__device__ __forceinline__ void sts2_pred(int pred, uint32_t p,
                                          u64 a, u64 b, u64 c, u64 d) {
    asm volatile(
        "{\n\t.reg .pred q;\n\t"
        "setp.ne.s32 q, %0, 0;\n\t"
        "@q st.shared.v2.u64 [%1], {%2,%3};\n\t"
        "@q st.shared.v2.u64 [%4], {%5,%6};\n\t}"
        :: "r"(pred), "r"(p), "l"(a), "l"(b), "r"(p + 16), "l"(c), "l"(d)
        : "memory");
}

// blocking parity wait, acquire at CLUSTER scope
__device__ __forceinline__ void mbar_wait_acq_cluster(uint32_t addr, uint32_t parity) {
    asm volatile(
        "{\n\t.reg .pred P1;\n\t"
        "WL_%=:\n\t"
        "mbarrier.try_wait.parity.acquire.cluster.shared::cta.b64 P1, [%0], %1, 0x989680;\n\t"
        "@P1 bra.uni WD_%=;\n\t"
        "bra.uni WL_%=;\n\t"
        "WD_%=:\n\t}"
        :: "r"(addr), "r"(parity) : "memory");
}

// blocking parity wait, acquire at CTA scope (writer)
__device__ __forceinline__ void mbar_wait_acq_cta(uint32_t addr, uint32_t parity) {
    asm volatile(
        "{\n\t.reg .pred P1;\n\t"
        "WL_%=:\n\t"
        "mbarrier.try_wait.parity.acquire.cta.shared::cta.b64 P1, [%0], %1, 0x989680;\n\t"
        "@P1 bra.uni WD_%=;\n\t"
        "bra.uni WL_%=;\n\t"
        "WD_%=:\n\t}"
        :: "r"(addr), "r"(parity) : "memory");
}

__global__ void __cluster_dims__(2, 1, 1) __launch_bounds__(THREADS, 1)
ks_kernel(const float* __restrict__ u0,
          const float* __restrict__ cp,
          const float* __restrict__ ap,
          const float* __restrict__ bp,
          float* __restrict__ out) {
    extern __shared__ char smem_raw[];
    Smem* sm = reinterpret_cast<Smem*>(smem_raw);

    const int row  = blockIdx.x >> 1;
    const int half = blockIdx.x & 1;
    const int w    = threadIdx.x >> 5;
    const int lane = threadIdx.x & 31;

    const uint32_t ring0  = (uint32_t)__cvta_generic_to_shared(&sm->ring[0][0]);
    const uint32_t shbase = (uint32_t)__cvta_generic_to_shared(&sm->sh_ex[0][0]);
    const uint32_t mbbase = (uint32_t)__cvta_generic_to_shared(&sm->mbar[0]);
    const uint32_t mbst   = (uint32_t)__cvta_generic_to_shared(&sm->mb_st);
    const uint32_t kda    = (uint32_t)__cvta_generic_to_shared(&sm->k_done);
    const uint32_t peer   = (uint32_t)(half ^ 1);
    const size_t   FR     = (size_t)BATCH * NSP;

    if (threadIdx.x == 0) {
        asm volatile("mbarrier.init.shared.b64 [%0], 1;" :: "r"(mbbase)     : "memory");
        asm volatile("mbarrier.init.shared.b64 [%0], 1;" :: "r"(mbbase + 8) : "memory");
        asm volatile("mbarrier.init.shared.b64 [%0], %1;" :: "r"(mbst), "r"(CWARPS) : "memory");
        sm->k_done = -1;
    }
    __syncthreads();
    asm volatile("barrier.cluster.arrive.aligned;" ::: "memory");
    asm volatile("barrier.cluster.wait.aligned;"   ::: "memory");

    if (w < CWARPS) {
        // ===================== COMPUTE WARP =====================
        const float dt = 0.01f;
        const float Af = -0.5f * dt * (*cp);
        const float Bc = -dt * (*ap);
        const float Cc = -dt * (*bp);
        const float c0f = 1.0f - 2.0f * Bc + 6.0f * Cc;
        const float c1f = Bc - 4.0f * Cc;
        const u64 C0 = pk(c0f, c0f), C1 = pk(c1f, c1f), C2 = pk(Cc, Cc);
        const u64 AV = pk(Af, Af),   M1 = pk(-1.0f, -1.0f);

        const int base = half * OWN_CTA + w * OWNW - GW;   // may be negative
        const int j0   = lane * EPT;
        const bool owned = (lane >= 8) && (lane < 24);     // [GW, GW+OWNW) lane-aligned
        const int  ownp  = owned ? 1 : 0;
        // ring staging address for this thread (owned lanes): 32 B contiguous
        const uint32_t stsb = ring0 + (uint32_t)((w * OWNW + (j0 - GW)) * 4);

        // ---- initial load ----
        u64 P[4];
        const float* urow = u0 + (size_t)row * NSP;
        #pragma unroll
        for (int g = 0; g < 2; g++) {
            int pos = (base + j0 + 4 * g) & (NSP - 1);
            float4 v = *reinterpret_cast<const float4*>(urow + pos);
            P[2 * g]     = pk(v.x, v.y);
            P[2 * g + 1] = pk(v.z, v.w);
        }

        // ---- frame 0 = u0 (one-time direct store) ----
        st2_pred(ownp, out + (size_t)row * NSP + base + j0, P[0], P[1], P[2], P[3]);

        int t = 0;
        #pragma unroll 1
        for (int seg = 0; seg < 32; seg++) {
            if (seg > 0) {
                // ===== ghost exchange (mbarrier handshake) =====
                const int n  = seg - 1;
                const int q  = n & 1;
                const uint32_t ph = (uint32_t)((n >> 1) & 1);
                const uint32_t mb = mbbase + (uint32_t)(q * 8);

                if (owned) {
                    float a, b, c, d;
                    float* s = &sm->sh_ex[q][w * OWNW + (j0 - GW)];
                    upk(P[0], a, b); upk(P[1], c, d);
                    reinterpret_cast<float4*>(s)[0] = make_float4(a, b, c, d);
                    upk(P[2], a, b); upk(P[3], c, d);
                    reinterpret_cast<float4*>(s)[1] = make_float4(a, b, c, d);
                }
                asm volatile("bar.sync 1, 256;" ::: "memory");

                if (threadIdx.x == 0) {
                    asm volatile(
                        "{\n\t.reg .b32 ra;\n\t"
                        "mapa.shared::cluster.u32 ra, %0, %1;\n\t"
                        "mbarrier.arrive.release.cluster.shared::cluster.b64 _, [ra];\n\t}"
                        :: "r"(mb), "r"(peer) : "memory");
                }
                mbar_wait_acq_cluster(mb, ph);

                if (!owned) {
                    #pragma unroll
                    for (int g = 0; g < 2; g++) {
                        int pos = (base + j0 + 4 * g) & (NSP - 1);
                        int h2  = pos >> 10;
                        int idx = pos & (OWN_CTA - 1);
                        float4 v;
                        if (h2 == half) {
                            v = *reinterpret_cast<const float4*>(&sm->sh_ex[q][idx]);
                        } else {
                            uint32_t pa;
                            asm("mapa.shared::cluster.u32 %0, %1, %2;"
                                : "=r"(pa)
                                : "r"(shbase + (uint32_t)((q * OWN_CTA + idx) * 4)),
                                  "r"(peer));
                            asm volatile("ld.shared::cluster.v4.f32 {%0,%1,%2,%3}, [%4];"
                                         : "=f"(v.x), "=f"(v.y), "=f"(v.z), "=f"(v.w)
                                         : "r"(pa));
                        }
                        P[2 * g]     = pk(v.x, v.y);
                        P[2 * g + 1] = pk(v.z, v.w);
                    }
                }
            }

            const int steps = (seg == 31) ? (NSTEP - 31 * KEX) : KEX;
            #pragma unroll 4
            for (int s = 0; s < steps; s++, t++) {
                if ((t & 3) == 0) {
                    // ring-space check: batch t>>2 overwrites batch (t>>2)-4
                    int kc = t >> 2, kd;
                    while (true) {
                        asm volatile("ld.acquire.cta.shared.b32 %0, [%1];"
                                     : "=r"(kd) : "r"(kda));
                        if (kc - kd <= 4) break;
                        __nanosleep(64);
                    }
                }

                // ===== one explicit-Euler step =====
                u64 prev = __shfl_up_sync(0xffffffffu, P[3], 1);
                u64 next = __shfl_down_sync(0xffffffffu, P[0], 1);

                u64 A[6];
                A[0] = prev; A[1] = P[0]; A[2] = P[1]; A[3] = P[2]; A[4] = P[3]; A[5] = next;
                float a[12];
                #pragma unroll
                for (int i = 0; i < 6; i++) upk(A[i], a[2 * i], a[2 * i + 1]);
                u64 O[5];
                #pragma unroll
                for (int i = 0; i < 5; i++) O[i] = pk(a[2 * i + 1], a[2 * i + 2]);

                u64 r[4];
                #pragma unroll
                for (int p = 0; p < 4; p++) {
                    u64 u   = A[p + 1];
                    u64 d1  = fma2(M1, O[p], O[p + 1]);
                    u64 t1  = fma2(AV, d1, C0);
                    u64 s1  = add2(O[p + 1], O[p]);
                    u64 s2  = add2(A[p + 2], A[p]);
                    u64 m   = mul2(C2, s2);
                    m       = fma2(C1, s1, m);
                    r[p]    = fma2(u, t1, m);
                }

                // stage frame t+1 into ring slot t&15 (predicated STS)
                sts2_pred(ownp, stsb + (uint32_t)((t & (NBUF - 1)) << 12),
                          r[0], r[1], r[2], r[3]);

                if ((t & 3) == 3) {
                    __syncwarp();
                    if (lane == 0)
                        asm volatile("mbarrier.arrive.release.cta.shared::cta.b64 _, [%0];"
                                     :: "r"(mbst) : "memory");
                }

                P[0] = r[0]; P[1] = r[1]; P[2] = r[2]; P[3] = r[3];
            }
        }
    } else {
        // ===================== WRITER WARP =====================
        if (lane == 0) {
            float* gb = out + (size_t)row * NSP + half * OWN_CTA;
            #pragma unroll 1
            for (int k = 0; k < NBATCH; k++) {
                mbar_wait_acq_cta(mbst, (uint32_t)(k & 1));
                asm volatile("fence.proxy.async.shared::cta;" ::: "memory");
                #pragma unroll
                for (int i = 0; i < FB; i++) {
                    int f = k * FB + i;                       // frame index - 1
                    uint32_t src = ring0 + (uint32_t)((f & (NBUF - 1)) << 12);
                    float* dst = gb + (size_t)(f + 1) * FR;
                    asm volatile("cp.async.bulk.global.shared::cta.bulk_group [%0], [%1], %2;"
                                 :: "l"(dst), "r"(src), "r"(4096u) : "memory");
                }
                asm volatile("cp.async.bulk.commit_group;" ::: "memory");
                asm volatile("cp.async.bulk.wait_group.read 2;" ::: "memory");
                if (k >= 2) {
                    int kd = k - 2;
                    asm volatile("st.release.cta.shared.b32 [%0], %1;"
                                 :: "r"(kda), "r"(kd) : "memory");
                }
            }
            asm volatile("cp.async.bulk.wait_group 0;" ::: "memory");
        }
    }

    // don't exit while peer may still access our SMEM / mbarriers
    asm volatile("barrier.cluster.arrive.aligned;" ::: "memory");
    asm volatile("barrier.cluster.wait.aligned;"   ::: "memory");
}

extern "C" void kernel_launch(void* const* d_in, const int* in_sizes, int n_in,
                              void* d_out, int out_size) {
    const float* u0    = (const float*)d_in[0];
    const float* c     = (const float*)d_in[1];
    const float* alpha = (const float*)d_in[2];
    const float* beta  = (const float*)d_in[3];
    float* out = (float*)d_out;

    cudaFuncSetAttribute(ks_kernel, cudaFuncAttributeMaxDynamicSharedMemorySize,
                         (int)sizeof(Smem));
    ks_kernel<<<BATCH * 2, THREADS, sizeof(Smem)>>>(u0, c, alpha, beta, out);
}

// round 16
// speedup vs baseline: 1.0535x; 1.0535x over previous
#include <cuda_runtime.h>
#include <cstdint>

#define NSP     2048
#define BATCH   64
#define NSTEP   1000
#define KEX     16            // steps between ghost exchanges
#define GW      32            // ghost width per side (= 2 * KEX)
#define OWNW    128           // owned elems per warp
#define COVER   192           // OWNW + 2*GW
#define EPT     6             // elems per thread (COVER/32) = 3 u64 pairs
#define THREADS 256           // 8 warps per CTA -> 2 warps/SMSP
#define OWN_CTA 1024          // owned per CTA (half row)

typedef unsigned long long u64;

__device__ __forceinline__ u64 pk(float lo, float hi) {
    u64 r; asm("mov.b64 %0,{%1,%2};" : "=l"(r) : "f"(lo), "f"(hi)); return r;
}
__device__ __forceinline__ void upk(u64 v, float& lo, float& hi) {
    asm("mov.b64 {%0,%1},%2;" : "=f"(lo), "=f"(hi) : "l"(v));
}
__device__ __forceinline__ u64 fma2(u64 a, u64 b, u64 c) {
    u64 d; asm("fma.rn.f32x2 %0,%1,%2,%3;" : "=l"(d) : "l"(a), "l"(b), "l"(c)); return d;
}
__device__ __forceinline__ u64 add2(u64 a, u64 b) {
    u64 d; asm("add.rn.f32x2 %0,%1,%2;" : "=l"(d) : "l"(a), "l"(b)); return d;
}
__device__ __forceinline__ u64 mul2(u64 a, u64 b) {
    u64 d; asm("mul.rn.f32x2 %0,%1,%2;" : "=l"(d) : "l"(a), "l"(b)); return d;
}

// three predicated 8B streaming global stores (branch-free)
__device__ __forceinline__ void st3_pred(int p0, int p1, int p2, float* p,
                                         u64 a, u64 b, u64 c) {
    asm volatile(
        "{\n\t.reg .pred q0,q1,q2;\n\t"
        "setp.ne.s32 q0,%0,0;\n\t"
        "setp.ne.s32 q1,%1,0;\n\t"
        "setp.ne.s32 q2,%2,0;\n\t"
        "@q0 st.global.cs.b64 [%3], %4;\n\t"
        "@q1 st.global.cs.b64 [%5], %6;\n\t"
        "@q2 st.global.cs.b64 [%7], %8;\n\t}"
        :: "r"(p0), "r"(p1), "r"(p2),
           "l"(p), "l"(a), "l"(p + 2), "l"(b), "l"(p + 4), "l"(c)
        : "memory");
}

// three predicated 8B shared stores (exchange publish)
__device__ __forceinline__ void sts3_pred(int p0, int p1, int p2, uint32_t p,
                                          u64 a, u64 b, u64 c) {
    asm volatile(
        "{\n\t.reg .pred q0,q1,q2;\n\t"
        "setp.ne.s32 q0,%0,0;\n\t"
        "setp.ne.s32 q1,%1,0;\n\t"
        "setp.ne.s32 q2,%2,0;\n\t"
        "@q0 st.shared.b64 [%3], %4;\n\t"
        "@q1 st.shared.b64 [%5], %6;\n\t"
        "@q2 st.shared.b64 [%7], %8;\n\t}"
        :: "r"(p0), "r"(p1), "r"(p2),
           "r"(p), "l"(a), "r"(p + 8), "l"(b), "r"(p + 16), "l"(c)
        : "memory");
}

// blocking parity wait, acquire at CLUSTER scope (peer's STS must be visible)
__device__ __forceinline__ void mbar_wait_acq_cluster(uint32_t addr, uint32_t parity) {
    asm volatile(
        "{\n\t.reg .pred P1;\n\t"
        "WL_%=:\n\t"
        "mbarrier.try_wait.parity.acquire.cluster.shared::cta.b64 P1, [%0], %1, 0x989680;\n\t"
        "@P1 bra.uni WD_%=;\n\t"
        "bra.uni WL_%=;\n\t"
        "WD_%=:\n\t}"
        :: "r"(addr), "r"(parity) : "memory");
}

__global__ void __cluster_dims__(2, 1, 1) __launch_bounds__(THREADS, 1)
ks_kernel(const float* __restrict__ u0,
          const float* __restrict__ cp,
          const float* __restrict__ ap,
          const float* __restrict__ bp,
          float* __restrict__ out) {
    __shared__ alignas(16) float sh_ex[2][OWN_CTA];   // double-buffered staging (8 KB)
    __shared__ alignas(8)  u64   mbar[2];             // one mbarrier per buffer parity

    const int row  = blockIdx.x >> 1;
    const int half = blockIdx.x & 1;
    const int w    = threadIdx.x >> 5;
    const int lane = threadIdx.x & 31;

    const float dt = 0.01f;
    const float Af = -0.5f * dt * (*cp);
    const float Bc = -dt * (*ap);
    const float Cc = -dt * (*bp);
    const float c0f = 1.0f - 2.0f * Bc + 6.0f * Cc;
    const float c1f = Bc - 4.0f * Cc;
    const u64 C0 = pk(c0f, c0f), C1 = pk(c1f, c1f), C2 = pk(Cc, Cc);
    const u64 AV = pk(Af, Af),   M1 = pk(-1.0f, -1.0f);

    const uint32_t shbase = (uint32_t)__cvta_generic_to_shared(&sh_ex[0][0]);
    const uint32_t mbbase = (uint32_t)__cvta_generic_to_shared(&mbar[0]);
    const uint32_t peer   = (uint32_t)(half ^ 1);

    if (threadIdx.x == 0) {
        asm volatile("mbarrier.init.shared.b64 [%0], 1;" :: "r"(mbbase)     : "memory");
        asm volatile("mbarrier.init.shared.b64 [%0], 1;" :: "r"(mbbase + 8) : "memory");
    }
    __syncthreads();
    asm volatile("barrier.cluster.arrive.aligned;" ::: "memory");
    asm volatile("barrier.cluster.wait.aligned;"   ::: "memory");

    // warp cover: local coord j in [0, COVER); global pos = base + j (mod NSP)
    const int base = half * OWN_CTA + w * OWNW - GW;   // may be negative (even)
    const int j0   = lane * EPT;                       // even

    // per-u64-pair ownership: pair k covers elems (j0+2k, j0+2k+1);
    // owned region [GW, GW+OWNW) = [32, 160); boundaries even -> no straddle
    const int ok0 = (j0     >= GW && j0     < GW + OWNW) ? 1 : 0;
    const int ok1 = (j0 + 2 >= GW && j0 + 2 < GW + OWNW) ? 1 : 0;
    const int ok2 = (j0 + 4 >= GW && j0 + 4 < GW + OWNW) ? 1 : 0;

    // ---- initial load: 3 u64 (8B) loads, periodic wrap ----
    u64 P0, P1, P2;
    {
        const float* urow = u0 + (size_t)row * NSP;
        int q0 = (base + j0)     & (NSP - 1);
        int q1 = (base + j0 + 2) & (NSP - 1);
        int q2 = (base + j0 + 4) & (NSP - 1);
        P0 = *reinterpret_cast<const u64*>(urow + q0);
        P1 = *reinterpret_cast<const u64*>(urow + q1);
        P2 = *reinterpret_cast<const u64*>(urow + q2);
    }

    // ---- frame 0 = u0 (predicated per-pair stores) ----
    st3_pred(ok0, ok1, ok2, out + (size_t)row * NSP + base + j0, P0, P1, P2);

    const size_t FR = (size_t)BATCH * NSP;
    float* op = out + FR + (size_t)row * NSP + (base + j0);   // frame 1 cursor

    // shared-address for publishing pair 0 (pairs 1,2 at +8/+16 bytes)
    // valid only when the corresponding pair is owned (predicated otherwise)
    const uint32_t pub_off = (uint32_t)((w * OWNW + (j0 - GW)) * 4);

    #pragma unroll 2
    for (int t = 0; t < NSTEP; t++) {
        if (t > 0 && (t & (KEX - 1)) == 0) {
            // ===== ghost exchange via mbarrier handshake =====
            const int n  = (t >> 4) - 1;                    // exchange index
            const int q  = n & 1;                           // buffer parity
            const uint32_t ph = (uint32_t)((n >> 1) & 1);   // mbar[q] phase
            const uint32_t mb = mbbase + (uint32_t)(q * 8);
            const uint32_t shq = shbase + (uint32_t)(q * OWN_CTA * 4);

            // publish owned pairs into sh_ex[q] (CTA-owned index space)
            sts3_pred(ok0, ok1, ok2, shq + pub_off, P0, P1, P2);
            __syncthreads();     // local STS done + prior-exchange reads done

            // signal peer: my sh_ex[q] ready (release at cluster scope)
            if (threadIdx.x == 0) {
                asm volatile(
                    "{\n\t.reg .b32 ra;\n\t"
                    "mapa.shared::cluster.u32 ra, %0, %1;\n\t"
                    "mbarrier.arrive.release.cluster.shared::cluster.b64 _, [ra];\n\t}"
                    :: "r"(mb), "r"(peer) : "memory");
            }
            mbar_wait_acq_cluster(mb, ph);

            // refill ghost pairs from own sh_ex[q] or peer sh_ex[q] (DSMEM)
            #pragma unroll
            for (int k = 0; k < 3; k++) {
                int ok = (k == 0) ? ok0 : (k == 1) ? ok1 : ok2;
                if (!ok) {
                    int pos = (base + j0 + 2 * k) & (NSP - 1);
                    int h2  = pos >> 10;              // owning half
                    int idx = pos & (OWN_CTA - 1);
                    u64 v;
                    if (h2 == half) {
                        asm volatile("ld.shared.b64 %0, [%1];"
                                     : "=l"(v) : "r"(shq + (uint32_t)(idx * 4)));
                    } else {
                        uint32_t pa;
                        asm("mapa.shared::cluster.u32 %0, %1, %2;"
                            : "=r"(pa) : "r"(shq + (uint32_t)(idx * 4)), "r"(peer));
                        asm volatile("ld.shared::cluster.b64 %0, [%1];"
                                     : "=l"(v) : "r"(pa));
                    }
                    if (k == 0) P0 = v; else if (k == 1) P1 = v; else P2 = v;
                }
            }
        }

        // ===== one explicit-Euler step: 2 u64 shuffles + 21 packed ops =====
        u64 prev = __shfl_up_sync(0xffffffffu, P2, 1);    // lane-1's pair (j0-2,j0-1)
        u64 next = __shfl_down_sync(0xffffffffu, P0, 1);  // lane+1's pair (j0+6,j0+7)

        // aligned pairs A[0..4] covering e[-2..7]
        float a0, a1, a2, a3, a4, a5, a6, a7, a8, a9;
        upk(prev, a0, a1); upk(P0, a2, a3); upk(P1, a4, a5);
        upk(P2, a6, a7);   upk(next, a8, a9);
        u64 O0 = pk(a1, a2);
        u64 O1 = pk(a3, a4);
        u64 O2 = pk(a5, a6);
        u64 O3 = pk(a7, a8);

        u64 r0, r1, r2;
        {   // pair 0: um2=prev, um1=O0, u=P0, up1=O1, up2=P1
            u64 d1 = fma2(M1, O0, O1);
            u64 t1 = fma2(AV, d1, C0);
            u64 s1 = add2(O1, O0);
            u64 s2 = add2(P1, prev);
            u64 m  = mul2(C2, s2);
            m      = fma2(C1, s1, m);
            r0     = fma2(P0, t1, m);
        }
        {   // pair 1: um2=P0, um1=O1, u=P1, up1=O2, up2=P2
            u64 d1 = fma2(M1, O1, O2);
            u64 t1 = fma2(AV, d1, C0);
            u64 s1 = add2(O2, O1);
            u64 s2 = add2(P2, P0);
            u64 m  = mul2(C2, s2);
            m      = fma2(C1, s1, m);
            r1     = fma2(P1, t1, m);
        }
        {   // pair 2: um2=P1, um1=O2, u=P2, up1=O3, up2=next
            u64 d1 = fma2(M1, O2, O3);
            u64 t1 = fma2(AV, d1, C0);
            u64 s1 = add2(O3, O2);
            u64 s2 = add2(next, P1);
            u64 m  = mul2(C2, s2);
            m      = fma2(C1, s1, m);
            r2     = fma2(P2, t1, m);
        }

        // trajectory frame t+1: predicated per-pair streaming stores
        st3_pred(ok0, ok1, ok2, op, r0, r1, r2);
        op += FR;

        P0 = r0; P1 = r1; P2 = r2;
    }

    // don't exit while peer may still access our SMEM / mbarriers
    asm volatile("barrier.cluster.arrive.aligned;" ::: "memory");
    asm volatile("barrier.cluster.wait.aligned;"   ::: "memory");
}

extern "C" void kernel_launch(void* const* d_in, const int* in_sizes, int n_in,
                              void* d_out, int out_size) {
    const float* u0    = (const float*)d_in[0];
    const float* c     = (const float*)d_in[1];
    const float* alpha = (const float*)d_in[2];
    const float* beta  = (const float*)d_in[3];
    float* out = (float*)d_out;

    ks_kernel<<<BATCH * 2, THREADS>>>(u0, c, alpha, beta, out);
}